// round 3
// baseline (speedup 1.0000x reference)
#include <cuda_runtime.h>
#include <math.h>
#include <stdint.h>
#include <stddef.h>

// Problem constants
#define SEQ   2048
#define BATCH 64
#define INF   512      // input features
#define H     512      // hidden
#define NGATE 1024     // 2H gate columns
#define NTOT  1536     // gate (1024) + cand (512) projection columns

// Persistent recurrence kernel config
#define G      64      // CTAs (all co-resident: 184KB smem -> 1 CTA/SM)
#define TPB    256
#define GCOLS  16      // gate columns per CTA   (64*16 = 1024)
#define CCOLS  8       // cand columns per CTA   (64*8  = 512)
#define WST    516     // padded smem column stride (bank spread)

// ---------------------------------------------------------------------------
// Scratch (static __device__: no runtime allocation)
// ---------------------------------------------------------------------------
__device__ float g_xproj[(size_t)SEQ * BATCH * NTOT];  // 805 MB: x@Wx + bias, all steps
__device__ float g_h[BATCH * H];
__device__ float g_rh[BATCH * H];
__device__ float g_z[BATCH * H];
__device__ unsigned int g_bar_count;
__device__ unsigned int g_bar_gen;

// ---------------------------------------------------------------------------
// Kernel 1: projection GEMM  P[m, n] = X[m,:] @ W[:, n] + bias[n]
//   m in [0, SEQ*BATCH), n in [0,1024): Wg_x / bg ; n in [1024,1536): Wc_x / bc
// ---------------------------------------------------------------------------
#define BM 64
#define BN 64
#define BK 16

__global__ void xproj_kernel(const float* __restrict__ X,
                             const float* __restrict__ Wg,
                             const float* __restrict__ bg,
                             const float* __restrict__ Wc,
                             const float* __restrict__ bc) {
    __shared__ float As[BK][BM + 4];   // transposed A tile
    __shared__ float Bs[BK][BN];

    const int tid = threadIdx.x;
    const int n0  = blockIdx.x * BN;
    const size_t m0 = (size_t)blockIdx.y * BM;

    const bool is_gate = (n0 < NGATE);
    const float* Bbase = is_gate ? (Wg + n0) : (Wc + (n0 - NGATE));
    const int    ldB   = is_gate ? NGATE : H;
    const float* bias  = is_gate ? (bg + n0) : (bc + (n0 - NGATE));

    const int tx = tid & 15;          // n-tile position
    const int ty = tid >> 4;          // m-tile position

    // global load assignments
    const int arow = tid >> 2;        // 0..63
    const int ak4  = (tid & 3) * 4;   // 0,4,8,12
    const int bk   = ty;              // 0..15
    const int bn4  = tx * 4;

    float acc[4][4];
#pragma unroll
    for (int i = 0; i < 4; i++)
#pragma unroll
        for (int j = 0; j < 4; j++) acc[i][j] = 0.f;

    for (int k0 = 0; k0 < INF; k0 += BK) {
        float4 av = *(const float4*)(X + (m0 + arow) * INF + k0 + ak4);
        As[ak4 + 0][arow] = av.x;
        As[ak4 + 1][arow] = av.y;
        As[ak4 + 2][arow] = av.z;
        As[ak4 + 3][arow] = av.w;
        *(float4*)&Bs[bk][bn4] =
            *(const float4*)(Bbase + (size_t)(k0 + bk) * ldB + bn4);
        __syncthreads();
#pragma unroll
        for (int k = 0; k < BK; k++) {
            float4 a = *(float4*)&As[k][ty * 4];
            float4 b = *(float4*)&Bs[k][tx * 4];
            acc[0][0] += a.x * b.x; acc[0][1] += a.x * b.y; acc[0][2] += a.x * b.z; acc[0][3] += a.x * b.w;
            acc[1][0] += a.y * b.x; acc[1][1] += a.y * b.y; acc[1][2] += a.y * b.z; acc[1][3] += a.y * b.w;
            acc[2][0] += a.z * b.x; acc[2][1] += a.z * b.y; acc[2][2] += a.z * b.z; acc[2][3] += a.z * b.w;
            acc[3][0] += a.w * b.x; acc[3][1] += a.w * b.y; acc[3][2] += a.w * b.z; acc[3][3] += a.w * b.w;
        }
        __syncthreads();
    }

    const float4 bv = *(const float4*)(bias + tx * 4);
#pragma unroll
    for (int i = 0; i < 4; i++) {
        float4 o;
        o.x = acc[i][0] + bv.x;
        o.y = acc[i][1] + bv.y;
        o.z = acc[i][2] + bv.z;
        o.w = acc[i][3] + bv.w;
        *(float4*)(g_xproj + (m0 + ty * 4 + i) * NTOT + n0 + tx * 4) = o;
    }
}

// ---------------------------------------------------------------------------
// h0 -> g_h
// ---------------------------------------------------------------------------
__global__ void init_h_kernel(const float* __restrict__ h0) {
    int i = blockIdx.x * blockDim.x + threadIdx.x;
    if (i < BATCH * H) g_h[i] = h0[i];
}

// ---------------------------------------------------------------------------
// Software grid barrier (sense via generation counter; survives graph replays
// because waiters capture the generation before arriving).
// ---------------------------------------------------------------------------
__device__ __forceinline__ void grid_barrier() {
    __threadfence();          // each thread publishes its own writes
    __syncthreads();
    if (threadIdx.x == 0) {
        unsigned int gen = *(volatile unsigned int*)&g_bar_gen;
        unsigned int a = atomicAdd(&g_bar_count, 1u);
        if (a == G - 1) {
            atomicExch(&g_bar_count, 0u);
            __threadfence();
            atomicAdd(&g_bar_gen, 1u);
        } else {
            while (*(volatile unsigned int*)&g_bar_gen == gen) { }
        }
    }
    __syncthreads();
}

// ---------------------------------------------------------------------------
// Kernel 2: persistent GRU recurrence.
//   CTA i owns gate cols [i*16, i*16+16) and cand cols [i*8, i*8+8).
//   Per step: phase1 gates (z,r -> g_z, g_rh), barrier,
//             phase2 cand + h update (-> g_h, out), barrier.
// ---------------------------------------------------------------------------
__global__ void __launch_bounds__(TPB, 1)
gru_persistent_kernel(const float* __restrict__ Wg,
                      const float* __restrict__ Wc,
                      float* __restrict__ out,
                      int write_hlast) {
    extern __shared__ float smem[];
    float* sW    = smem;                       // 24 cols * WST
    float* sh    = sW + 24 * WST;              // 64 * 512 (h, then rh)
    float* sHold = sh + BATCH * H;             // 64 * 8 (old h for my cand cols)
    float* sZ    = sHold + BATCH * CCOLS;      // 64 * 8

    const int cta = blockIdx.x;
    const int tid = threadIdx.x;
    const int gc0 = cta * GCOLS;
    const int cc0 = cta * CCOLS;

    // Load resident weight slices (Wg_h rows INF.., Wc_h rows INF..)
    for (int i = tid; i < GCOLS * INF; i += TPB) {
        int c = i & (GCOLS - 1);
        int k = i >> 4;
        sW[c * WST + k] = Wg[(size_t)(INF + k) * NGATE + gc0 + c];
    }
    for (int i = tid; i < CCOLS * INF; i += TPB) {
        int c = i & (CCOLS - 1);
        int k = i >> 3;
        sW[(GCOLS + c) * WST + k] = Wc[(size_t)(INF + k) * H + cc0 + c];
    }
    __syncthreads();

    // phase1 thread mapping: col in [0,16), 4 consecutive batches
    const int p1col = tid & 15;
    const int p1b0  = (tid >> 4) * 4;
    const int gcol  = gc0 + p1col;
    const float* wg = sW + p1col * WST;

    // phase2 thread mapping: col in [0,8), 2 consecutive batches
    const int p2col = tid & 7;
    const int p2b0  = (tid >> 3) * 2;
    const int ccol  = cc0 + p2col;
    const float* wc = sW + (GCOLS + p2col) * WST;

    for (int t = 0; t < SEQ; t++) {
        // ---- load h into smem (fresh from L2) ----
        const float4* hsrc = (const float4*)g_h;
        float4* hdst = (float4*)sh;
        for (int i = tid; i < (BATCH * H) / 4; i += TPB) hdst[i] = __ldcg(hsrc + i);
        __syncthreads();

        // ---- phase 1: gates ----
        {
            const size_t xrow = ((size_t)t * BATCH + p1b0) * NTOT + gcol;
            float xg0 = __ldg(g_xproj + xrow);
            float xg1 = __ldg(g_xproj + xrow + NTOT);
            float xg2 = __ldg(g_xproj + xrow + 2 * NTOT);
            float xg3 = __ldg(g_xproj + xrow + 3 * NTOT);

            float a0 = 0.f, a1 = 0.f, a2 = 0.f, a3 = 0.f;
            const float* h0p = sh + (p1b0 + 0) * H;
            const float* h1p = h0p + H;
            const float* h2p = h1p + H;
            const float* h3p = h2p + H;
#pragma unroll 4
            for (int k = 0; k < INF; k += 4) {
                float4 w  = *(const float4*)(wg + k);
                float4 v0 = *(const float4*)(h0p + k);
                float4 v1 = *(const float4*)(h1p + k);
                float4 v2 = *(const float4*)(h2p + k);
                float4 v3 = *(const float4*)(h3p + k);
                a0 += w.x * v0.x + w.y * v0.y + w.z * v0.z + w.w * v0.w;
                a1 += w.x * v1.x + w.y * v1.y + w.z * v1.z + w.w * v1.w;
                a2 += w.x * v2.x + w.y * v2.y + w.z * v2.z + w.w * v2.w;
                a3 += w.x * v3.x + w.y * v3.y + w.z * v3.z + w.w * v3.w;
            }
            float gv[4] = {a0 + xg0, a1 + xg1, a2 + xg2, a3 + xg3};
#pragma unroll
            for (int j = 0; j < 4; j++) {
                float s = 1.f / (1.f + expf(-gv[j]));
                int b = p1b0 + j;
                if (gcol < H) {
                    g_z[b * H + gcol] = s;
                } else {
                    int jc = gcol - H;
                    g_rh[b * H + jc] = s * sh[b * H + jc];
                }
            }
        }
        grid_barrier();   // z, rh globally visible

        // ---- stash old h + z for my cand cols, then overwrite sh with rh ----
        for (int i = tid; i < BATCH * CCOLS; i += TPB) {
            int b = i >> 3;
            int c = i & 7;
            sHold[i] = sh[b * H + cc0 + c];
            sZ[i]    = __ldcg(g_z + b * H + cc0 + c);
        }
        __syncthreads();
        {
            const float4* rsrc = (const float4*)g_rh;
            float4* rdst = (float4*)sh;
            for (int i = tid; i < (BATCH * H) / 4; i += TPB) rdst[i] = __ldcg(rsrc + i);
        }
        __syncthreads();

        // ---- phase 2: candidate + h update ----
        {
            const size_t xrow = ((size_t)t * BATCH + p2b0) * NTOT + NGATE + ccol;
            float xc0 = __ldg(g_xproj + xrow);
            float xc1 = __ldg(g_xproj + xrow + NTOT);

            float a0 = 0.f, a1 = 0.f;
            const float* r0p = sh + (p2b0 + 0) * H;
            const float* r1p = r0p + H;
#pragma unroll 4
            for (int k = 0; k < INF; k += 4) {
                float4 w  = *(const float4*)(wc + k);
                float4 v0 = *(const float4*)(r0p + k);
                float4 v1 = *(const float4*)(r1p + k);
                a0 += w.x * v0.x + w.y * v0.y + w.z * v0.z + w.w * v0.w;
                a1 += w.x * v1.x + w.y * v1.y + w.z * v1.z + w.w * v1.w;
            }
            float cand[2] = {tanhf(a0 + xc0), tanhf(a1 + xc1)};
#pragma unroll
            for (int j = 0; j < 2; j++) {
                int b = p2b0 + j;
                float hold = sHold[b * CCOLS + p2col];
                float z    = sZ[b * CCOLS + p2col];
                float hn   = hold + z * (cand[j] - hold);
                g_h[b * H + ccol] = hn;
                out[((size_t)t * BATCH + b) * H + ccol] = hn;
                if (write_hlast && t == SEQ - 1)
                    out[(size_t)SEQ * BATCH * H + b * H + ccol] = hn;
            }
        }
        grid_barrier();   // g_h globally visible for next step
    }
}

// ---------------------------------------------------------------------------
// Launch
// ---------------------------------------------------------------------------
extern "C" void kernel_launch(void* const* d_in, const int* in_sizes, int n_in,
                              void* d_out, int out_size) {
    const float* x  = (const float*)d_in[0];
    const float* h0 = (const float*)d_in[1];
    const float* Wg = (const float*)d_in[2];
    const float* bg = (const float*)d_in[3];
    const float* Wc = (const float*)d_in[4];
    const float* bc = (const float*)d_in[5];
    float* out = (float*)d_out;

    (void)in_sizes; (void)n_in;

    // 1) projections for all timesteps
    dim3 g1(NTOT / BN, (SEQ * BATCH) / BM);
    xproj_kernel<<<g1, 256>>>(x, Wg, bg, Wc, bc);

    // 2) h0 -> g_h
    init_h_kernel<<<(BATCH * H + 255) / 256, 256>>>(h0);

    // 3) persistent recurrence
    const int smem_bytes = (24 * WST + BATCH * H + 2 * BATCH * CCOLS) * (int)sizeof(float);
    cudaFuncSetAttribute(gru_persistent_kernel,
                         cudaFuncAttributeMaxDynamicSharedMemorySize, smem_bytes);
    int write_hlast = (out_size >= SEQ * BATCH * H + BATCH * H) ? 1 : 0;
    gru_persistent_kernel<<<G, TPB, smem_bytes>>>(Wg, Wc, out, write_hlast);
}

// round 7
// speedup vs baseline: 1.3450x; 1.3450x over previous
#include <cuda_runtime.h>
#include <math.h>
#include <stdint.h>
#include <stddef.h>

// Problem constants
#define SEQ   2048
#define BATCH 64
#define INF   512
#define H     512
#define NGATE 1024
#define NTOT  1536

// Recurrence config (G=64 proven co-resident in round 3)
#define G      64
#define TPB    512
#define WST    516     // padded smem row stride (floats)

// ---------------------------------------------------------------------------
// Scratch
// ---------------------------------------------------------------------------
__device__ float g_xproj[(size_t)SEQ * BATCH * NTOT];
__device__ float g_h[BATCH * H];
__device__ float g_rh[BATCH * H];
__device__ unsigned int g_bar_count;
__device__ unsigned int g_bar_gen;

// ---------------------------------------------------------------------------
// Kernel 1: projection GEMM, 128x128x8 tiles, 8x8 per thread (split fragments)
//   P[m, n] = X[m,:] @ W[:, n] + bias[n]
// ---------------------------------------------------------------------------
#define XBM 128
#define XBN 128
#define XBK 8

__global__ void __launch_bounds__(256, 2)
xproj_kernel(const float* __restrict__ X,
             const float* __restrict__ Wg,
             const float* __restrict__ bg,
             const float* __restrict__ Wc,
             const float* __restrict__ bc) {
    __shared__ float As[XBK][XBM + 4];
    __shared__ float Bs[XBK][XBN + 4];

    const int tid = threadIdx.x;
    const int n0  = blockIdx.x * XBN;
    const size_t m0 = (size_t)blockIdx.y * XBM;

    const bool is_gate = (n0 < NGATE);
    const float* Bbase = is_gate ? (Wg + n0) : (Wc + (n0 - NGATE));
    const int    ldB   = is_gate ? NGATE : H;
    const float* bias  = is_gate ? (bg + n0) : (bc + (n0 - NGATE));

    // global load mapping
    const int am = tid >> 1;          // 0..127
    const int ak = (tid & 1) * 4;     // 0 or 4
    const int br = tid >> 5;          // 0..7
    const int bn = (tid & 31) * 4;    // 0..124

    // compute mapping: two 4-wide fragments per dim, 64 apart
    const int tm4 = (tid >> 4) * 4;   // 0..60
    const int tn4 = (tid & 15) * 4;   // 0..60

    float acc[8][8];
#pragma unroll
    for (int i = 0; i < 8; i++)
#pragma unroll
        for (int j = 0; j < 8; j++) acc[i][j] = 0.f;

    float4 av = *(const float4*)(X + (m0 + am) * INF + ak);
    float4 bv = *(const float4*)(Bbase + (size_t)br * ldB + bn);

    for (int k0 = 0; k0 < INF; k0 += XBK) {
        As[ak + 0][am] = av.x;
        As[ak + 1][am] = av.y;
        As[ak + 2][am] = av.z;
        As[ak + 3][am] = av.w;
        *(float4*)&Bs[br][bn] = bv;
        __syncthreads();

        if (k0 + XBK < INF) {
            av = *(const float4*)(X + (m0 + am) * INF + k0 + XBK + ak);
            bv = *(const float4*)(Bbase + (size_t)(k0 + XBK + br) * ldB + bn);
        }

#pragma unroll
        for (int k = 0; k < XBK; k++) {
            float4 a0 = *(float4*)&As[k][tm4];
            float4 a1 = *(float4*)&As[k][64 + tm4];
            float4 b0 = *(float4*)&Bs[k][tn4];
            float4 b1 = *(float4*)&Bs[k][64 + tn4];
            float af[8] = {a0.x, a0.y, a0.z, a0.w, a1.x, a1.y, a1.z, a1.w};
            float bf[8] = {b0.x, b0.y, b0.z, b0.w, b1.x, b1.y, b1.z, b1.w};
#pragma unroll
            for (int i = 0; i < 8; i++)
#pragma unroll
                for (int j = 0; j < 8; j++)
                    acc[i][j] += af[i] * bf[j];
        }
        __syncthreads();
    }

    const float4 bv0 = *(const float4*)(bias + tn4);
    const float4 bv1 = *(const float4*)(bias + 64 + tn4);
    const float bb[8] = {bv0.x, bv0.y, bv0.z, bv0.w, bv1.x, bv1.y, bv1.z, bv1.w};
#pragma unroll
    for (int i = 0; i < 8; i++) {
        const size_t row = m0 + ((i < 4) ? (tm4 + i) : (64 + tm4 + i - 4));
        float4 o0, o1;
        o0.x = acc[i][0] + bb[0]; o0.y = acc[i][1] + bb[1];
        o0.z = acc[i][2] + bb[2]; o0.w = acc[i][3] + bb[3];
        o1.x = acc[i][4] + bb[4]; o1.y = acc[i][5] + bb[5];
        o1.z = acc[i][6] + bb[6]; o1.w = acc[i][7] + bb[7];
        float* orow = g_xproj + row * NTOT + n0;
        *(float4*)(orow + tn4)      = o0;
        *(float4*)(orow + 64 + tn4) = o1;
    }
}

// ---------------------------------------------------------------------------
// h0 -> g_h
// ---------------------------------------------------------------------------
__global__ void init_h_kernel(const float* __restrict__ h0) {
    int i = blockIdx.x * blockDim.x + threadIdx.x;
    if (i < BATCH * H) g_h[i] = h0[i];
}

// ---------------------------------------------------------------------------
// Software grid barrier (identical to round-3 proven version)
// ---------------------------------------------------------------------------
__device__ __forceinline__ void grid_barrier() {
    __threadfence();
    __syncthreads();
    if (threadIdx.x == 0) {
        unsigned int gen = *(volatile unsigned int*)&g_bar_gen;
        unsigned int a = atomicAdd(&g_bar_count, 1u);
        if (a == G - 1) {
            atomicExch(&g_bar_count, 0u);
            __threadfence();
            atomicAdd(&g_bar_gen, 1u);
        } else {
            while (*(volatile unsigned int*)&g_bar_gen == gen) { }
        }
    }
    __syncthreads();
}

// ---------------------------------------------------------------------------
// Kernel 2: persistent GRU recurrence, G=64 CTAs.
//   CTA i owns cols [8i, 8i+8) for z, r AND cand (z, hold stay in SMEM).
//   Phase1: 16 gate cols x 64 batches, 4x4 register blocks, split-K 8.
//   Phase2: 8 cand cols x 64 batches, 4x4 register blocks, split-K 16.
//   h / rh staged to SMEM via __ldcg float4.
// ---------------------------------------------------------------------------
__global__ void __launch_bounds__(TPB, 1)
gru_persistent_kernel(const float* __restrict__ Wg,
                      const float* __restrict__ Wc,
                      float* __restrict__ out,
                      int write_hlast) {
    extern __shared__ float smem[];
    float* sW    = smem;                 // 24 cols * WST (z:0-7, r:8-15, c:16-23)
    float* sh    = sW + 24 * WST;        // 64 * WST (h, then rh)
    float* sPart = sh + 64 * WST;        // 8192 split-K partials
    float* sZ    = sPart + 8192;         // 64 * 8
    float* sHold = sZ + 512;             // 64 * 8

    const int cta = blockIdx.x;
    const int tid = threadIdx.x;
    const int c0  = cta * 8;             // global column base (z, r, cand)

    // resident weights: 24 columns of 512
    for (int i = tid; i < 24 * INF; i += TPB) {
        int j = i >> 9;          // 0..23
        int k = i & (INF - 1);
        float v;
        if (j < 8)       v = Wg[(size_t)(INF + k) * NGATE + c0 + j];
        else if (j < 16) v = Wg[(size_t)(INF + k) * NGATE + H + c0 + (j - 8)];
        else             v = Wc[(size_t)(INF + k) * H + c0 + (j - 16)];
        sW[j * WST + k] = v;
    }
    __syncthreads();

    // phase1 mapping: cg in [0,4), bg in [0,16), ks1 in [0,8)
    const int cg  = tid & 3;
    const int bg1 = (tid >> 2) & 15;
    const int k1  = (tid >> 6) * 64;     // K-slice start
    // phase2 mapping: cg2 in [0,2), bg2 in [0,16), ks2 in [0,16)
    const int cg2 = tid & 1;
    const int bg2 = (tid >> 1) & 15;
    const int k2  = (tid >> 5) * 32;

    // reduction output indices
    const int o1a = tid;          // phase1 outputs tid, tid+512
    const int c1a = o1a >> 6, b1a = o1a & 63;
    const int o1b = tid + 512;
    const int c1b = o1b >> 6, b1b = o1b & 63;
    const int gcol_a = (c1a < 8) ? (c0 + c1a) : (H + c0 + (c1a - 8));
    const int gcol_b = (c1b < 8) ? (c0 + c1b) : (H + c0 + (c1b - 8));
    const int c2o = tid >> 6, b2o = tid & 63;   // phase2 output

    for (int t = 0; t < SEQ; t++) {
        // prefetch x-projections for this step's outputs
        const size_t xbase = (size_t)t * BATCH * NTOT;
        float xg0 = __ldg(g_xproj + xbase + (size_t)b1a * NTOT + gcol_a);
        float xg1 = __ldg(g_xproj + xbase + (size_t)b1b * NTOT + gcol_b);

        // ---- stage h into smem ----
        {
            const float* src = g_h;
#pragma unroll
            for (int n = 0; n < 16; n++) {
                int i = tid + n * 512;           // 0..8191 float4 slots
                int row = i >> 7;
                int cc  = (i & 127) * 4;
                *(float4*)(sh + row * WST + cc) =
                    __ldcg((const float4*)(src + row * H + cc));
            }
        }
        __syncthreads();

        // ---- phase 1 main loop: acc[i][j], col cg+4i, batch bg1+16j ----
        {
            float acc[4][4];
#pragma unroll
            for (int i = 0; i < 4; i++)
#pragma unroll
                for (int j = 0; j < 4; j++) acc[i][j] = 0.f;

            const float* w0 = sW + (cg + 0)  * WST + k1;
            const float* w1 = sW + (cg + 4)  * WST + k1;
            const float* w2 = sW + (cg + 8)  * WST + k1;
            const float* w3 = sW + (cg + 12) * WST + k1;
            const float* h0p = sh + (bg1 + 0)  * WST + k1;
            const float* h1p = sh + (bg1 + 16) * WST + k1;
            const float* h2p = sh + (bg1 + 32) * WST + k1;
            const float* h3p = sh + (bg1 + 48) * WST + k1;

#pragma unroll 4
            for (int kk = 0; kk < 64; kk += 4) {
                float4 w[4], h[4];
                w[0] = *(const float4*)(w0 + kk);
                w[1] = *(const float4*)(w1 + kk);
                w[2] = *(const float4*)(w2 + kk);
                w[3] = *(const float4*)(w3 + kk);
                h[0] = *(const float4*)(h0p + kk);
                h[1] = *(const float4*)(h1p + kk);
                h[2] = *(const float4*)(h2p + kk);
                h[3] = *(const float4*)(h3p + kk);
#pragma unroll
                for (int i = 0; i < 4; i++)
#pragma unroll
                    for (int j = 0; j < 4; j++)
                        acc[i][j] += w[i].x * h[j].x + w[i].y * h[j].y +
                                     w[i].z * h[j].z + w[i].w * h[j].w;
            }
            const int ks1 = tid >> 6;
#pragma unroll
            for (int i = 0; i < 4; i++)
#pragma unroll
                for (int j = 0; j < 4; j++)
                    sPart[ks1 * 1024 + (cg + 4 * i) * 64 + (bg1 + 16 * j)] = acc[i][j];
        }
        __syncthreads();

        // ---- phase 1 reduction + activation (2 outputs/thread) ----
        {
            float s0 = xg0, s1 = xg1;
#pragma unroll
            for (int s = 0; s < 8; s++) {
                s0 += sPart[s * 1024 + o1a];
                s1 += sPart[s * 1024 + o1b];
            }
            float sig0 = 1.f / (1.f + expf(-s0));
            float sig1 = 1.f / (1.f + expf(-s1));
            if (c1a < 8) sZ[b1a * 8 + c1a] = sig0;
            else {
                int cc = c1a - 8;
                g_rh[b1a * H + c0 + cc] = sig0 * sh[b1a * WST + c0 + cc];
            }
            if (c1b < 8) sZ[b1b * 8 + c1b] = sig1;
            else {
                int cc = c1b - 8;
                g_rh[b1b * H + c0 + cc] = sig1 * sh[b1b * WST + c0 + cc];
            }
        }
        // stash old h for my cand cols (sh overwritten by rh after barrier)
        {
            int b = tid >> 3, c = tid & 7;
            sHold[tid] = sh[b * WST + c0 + c];
        }
        grid_barrier();   // publish g_rh

        // prefetch cand x-projection
        float xc = __ldg(g_xproj + xbase + (size_t)b2o * NTOT + NGATE + c0 + c2o);

        // ---- stage rh into smem ----
        {
            const float* src = g_rh;
#pragma unroll
            for (int n = 0; n < 16; n++) {
                int i = tid + n * 512;
                int row = i >> 7;
                int cc  = (i & 127) * 4;
                *(float4*)(sh + row * WST + cc) =
                    __ldcg((const float4*)(src + row * H + cc));
            }
        }
        __syncthreads();

        // ---- phase 2 main loop: col cg2+2i, batch bg2+16j ----
        {
            float acc[4][4];
#pragma unroll
            for (int i = 0; i < 4; i++)
#pragma unroll
                for (int j = 0; j < 4; j++) acc[i][j] = 0.f;

            const float* w0 = sW + (16 + cg2 + 0) * WST + k2;
            const float* w1 = sW + (16 + cg2 + 2) * WST + k2;
            const float* w2 = sW + (16 + cg2 + 4) * WST + k2;
            const float* w3 = sW + (16 + cg2 + 6) * WST + k2;
            const float* r0p = sh + (bg2 + 0)  * WST + k2;
            const float* r1p = sh + (bg2 + 16) * WST + k2;
            const float* r2p = sh + (bg2 + 32) * WST + k2;
            const float* r3p = sh + (bg2 + 48) * WST + k2;

#pragma unroll 4
            for (int kk = 0; kk < 32; kk += 4) {
                float4 w[4], h[4];
                w[0] = *(const float4*)(w0 + kk);
                w[1] = *(const float4*)(w1 + kk);
                w[2] = *(const float4*)(w2 + kk);
                w[3] = *(const float4*)(w3 + kk);
                h[0] = *(const float4*)(r0p + kk);
                h[1] = *(const float4*)(r1p + kk);
                h[2] = *(const float4*)(r2p + kk);
                h[3] = *(const float4*)(r3p + kk);
#pragma unroll
                for (int i = 0; i < 4; i++)
#pragma unroll
                    for (int j = 0; j < 4; j++)
                        acc[i][j] += w[i].x * h[j].x + w[i].y * h[j].y +
                                     w[i].z * h[j].z + w[i].w * h[j].w;
            }
            const int ks2 = tid >> 5;
#pragma unroll
            for (int i = 0; i < 4; i++)
#pragma unroll
                for (int j = 0; j < 4; j++)
                    sPart[ks2 * 512 + (cg2 + 2 * i) * 64 + (bg2 + 16 * j)] = acc[i][j];
        }
        __syncthreads();

        // ---- phase 2 reduction + h update (1 output/thread) ----
        {
            float sum = xc;
#pragma unroll
            for (int s = 0; s < 16; s++) sum += sPart[s * 512 + tid];
            float cand = tanhf(sum);
            float hold = sHold[b2o * 8 + c2o];
            float z    = sZ[b2o * 8 + c2o];
            float hn   = hold + z * (cand - hold);
            g_h[b2o * H + c0 + c2o] = hn;
            out[((size_t)t * BATCH + b2o) * H + c0 + c2o] = hn;
            if (write_hlast && t == SEQ - 1)
                out[(size_t)SEQ * BATCH * H + b2o * H + c0 + c2o] = hn;
        }
        grid_barrier();   // publish g_h for next step
    }
}

// ---------------------------------------------------------------------------
// Launch
// ---------------------------------------------------------------------------
extern "C" void kernel_launch(void* const* d_in, const int* in_sizes, int n_in,
                              void* d_out, int out_size) {
    const float* x  = (const float*)d_in[0];
    const float* h0 = (const float*)d_in[1];
    const float* Wg = (const float*)d_in[2];
    const float* bg = (const float*)d_in[3];
    const float* Wc = (const float*)d_in[4];
    const float* bc = (const float*)d_in[5];
    float* out = (float*)d_out;

    (void)in_sizes; (void)n_in;

    dim3 g1(NTOT / XBN, (SEQ * BATCH) / XBM);
    xproj_kernel<<<g1, 256>>>(x, Wg, bg, Wc, bc);

    init_h_kernel<<<(BATCH * H + 255) / 256, 256>>>(h0);

    const int smem_bytes = (24 * WST + 64 * WST + 8192 + 512 + 512) * (int)sizeof(float);
    cudaFuncSetAttribute(gru_persistent_kernel,
                         cudaFuncAttributeMaxDynamicSharedMemorySize, smem_bytes);
    int write_hlast = (out_size >= SEQ * BATCH * H + BATCH * H) ? 1 : 0;
    gru_persistent_kernel<<<G, TPB, smem_bytes>>>(Wg, Wc, out, write_hlast);
}

// round 9
// speedup vs baseline: 2.0115x; 1.4956x over previous
#include <cuda_runtime.h>
#include <math.h>
#include <stdint.h>
#include <stddef.h>

// Problem constants
#define SEQ   2048
#define BATCH 64
#define INF   512
#define H     512
#define NGATE 1024
#define NTOT  1536

// Recurrence config: 128 CTAs = 64 col-groups x 2 batch-halves
#define G      128
#define TPB    512
#define WST    516     // padded smem row stride (floats)
#define BROWS  32      // batches per CTA

// split-K partial layouts (conflict-free: bank = 8*cg + bg)
#define P1SL   640     // phase1 slice stride (16 cols * 40)
#define P2SL   336     // phase2 slice stride (8 cols * 40, padded)
#define CSTR   40      // per-column stride inside a slice

// ---------------------------------------------------------------------------
// Scratch
// ---------------------------------------------------------------------------
__device__ float g_xproj[(size_t)SEQ * BATCH * NTOT];
__device__ float g_h[BATCH * H];
__device__ float g_rh[BATCH * H];
__device__ unsigned int g_bar_count;
__device__ unsigned int g_bar_gen;

// ---------------------------------------------------------------------------
// Kernel 1: projection GEMM (unchanged from round 7 — passed, fma 70.5%)
// ---------------------------------------------------------------------------
#define XBM 128
#define XBN 128
#define XBK 8

__global__ void __launch_bounds__(256, 2)
xproj_kernel(const float* __restrict__ X,
             const float* __restrict__ Wg,
             const float* __restrict__ bg,
             const float* __restrict__ Wc,
             const float* __restrict__ bc) {
    __shared__ float As[XBK][XBM + 4];
    __shared__ float Bs[XBK][XBN + 4];

    const int tid = threadIdx.x;
    const int n0  = blockIdx.x * XBN;
    const size_t m0 = (size_t)blockIdx.y * XBM;

    const bool is_gate = (n0 < NGATE);
    const float* Bbase = is_gate ? (Wg + n0) : (Wc + (n0 - NGATE));
    const int    ldB   = is_gate ? NGATE : H;
    const float* bias  = is_gate ? (bg + n0) : (bc + (n0 - NGATE));

    const int am = tid >> 1;
    const int ak = (tid & 1) * 4;
    const int br = tid >> 5;
    const int bn = (tid & 31) * 4;

    const int tm4 = (tid >> 4) * 4;
    const int tn4 = (tid & 15) * 4;

    float acc[8][8];
#pragma unroll
    for (int i = 0; i < 8; i++)
#pragma unroll
        for (int j = 0; j < 8; j++) acc[i][j] = 0.f;

    float4 av = *(const float4*)(X + (m0 + am) * INF + ak);
    float4 bv = *(const float4*)(Bbase + (size_t)br * ldB + bn);

    for (int k0 = 0; k0 < INF; k0 += XBK) {
        As[ak + 0][am] = av.x;
        As[ak + 1][am] = av.y;
        As[ak + 2][am] = av.z;
        As[ak + 3][am] = av.w;
        *(float4*)&Bs[br][bn] = bv;
        __syncthreads();

        if (k0 + XBK < INF) {
            av = *(const float4*)(X + (m0 + am) * INF + k0 + XBK + ak);
            bv = *(const float4*)(Bbase + (size_t)(k0 + XBK + br) * ldB + bn);
        }

#pragma unroll
        for (int k = 0; k < XBK; k++) {
            float4 a0 = *(float4*)&As[k][tm4];
            float4 a1 = *(float4*)&As[k][64 + tm4];
            float4 b0 = *(float4*)&Bs[k][tn4];
            float4 b1 = *(float4*)&Bs[k][64 + tn4];
            float af[8] = {a0.x, a0.y, a0.z, a0.w, a1.x, a1.y, a1.z, a1.w};
            float bf[8] = {b0.x, b0.y, b0.z, b0.w, b1.x, b1.y, b1.z, b1.w};
#pragma unroll
            for (int i = 0; i < 8; i++)
#pragma unroll
                for (int j = 0; j < 8; j++)
                    acc[i][j] += af[i] * bf[j];
        }
        __syncthreads();
    }

    const float4 bv0 = *(const float4*)(bias + tn4);
    const float4 bv1 = *(const float4*)(bias + 64 + tn4);
    const float bb[8] = {bv0.x, bv0.y, bv0.z, bv0.w, bv1.x, bv1.y, bv1.z, bv1.w};
#pragma unroll
    for (int i = 0; i < 8; i++) {
        const size_t row = m0 + ((i < 4) ? (tm4 + i) : (64 + tm4 + i - 4));
        float4 o0, o1;
        o0.x = acc[i][0] + bb[0]; o0.y = acc[i][1] + bb[1];
        o0.z = acc[i][2] + bb[2]; o0.w = acc[i][3] + bb[3];
        o1.x = acc[i][4] + bb[4]; o1.y = acc[i][5] + bb[5];
        o1.z = acc[i][6] + bb[6]; o1.w = acc[i][7] + bb[7];
        float* orow = g_xproj + row * NTOT + n0;
        *(float4*)(orow + tn4)      = o0;
        *(float4*)(orow + 64 + tn4) = o1;
    }
}

// ---------------------------------------------------------------------------
// h0 -> g_h
// ---------------------------------------------------------------------------
__global__ void init_h_kernel(const float* __restrict__ h0) {
    int i = blockIdx.x * blockDim.x + threadIdx.x;
    if (i < BATCH * H) g_h[i] = h0[i];
}

// ---------------------------------------------------------------------------
// Software grid barrier (round-3/7 proven form, plain spin)
// ---------------------------------------------------------------------------
__device__ __forceinline__ void grid_barrier() {
    __threadfence();
    __syncthreads();
    if (threadIdx.x == 0) {
        unsigned int gen = *(volatile unsigned int*)&g_bar_gen;
        unsigned int a = atomicAdd(&g_bar_count, 1u);
        if (a == G - 1) {
            atomicExch(&g_bar_count, 0u);
            __threadfence();
            atomicAdd(&g_bar_gen, 1u);
        } else {
            while (*(volatile unsigned int*)&g_bar_gen == gen) { }
        }
    }
    __syncthreads();
}

// ---------------------------------------------------------------------------
// Kernel 2: persistent GRU recurrence, 128 CTAs.
//   CTA i: col-group (i>>1)*8 for z/r/cand, batch half (i&1)*32.
//   Phase1: 16 gate cols x 32 batches, 4x4 blocks, split-K 16 (32 K each).
//   Phase2: 8 cand cols x 32 batches, 4x4 blocks, split-K 32 (16 K each).
// ---------------------------------------------------------------------------
__global__ void __launch_bounds__(TPB, 1)
gru_persistent_kernel(const float* __restrict__ Wg,
                      const float* __restrict__ Wc,
                      float* __restrict__ out,
                      int write_hlast) {
    extern __shared__ float smem[];
    float* sW    = smem;                 // 24 cols * WST (z:0-7, r:8-15, c:16-23)
    float* sh    = sW + 24 * WST;        // 32 rows * WST (h, then rh)
    float* sPart = sh + BROWS * WST;     // max(16*P1SL, 32*P2SL) = 10752
    float* sZ    = sPart + 10752;        // 32 * 8
    float* sHold = sZ + BROWS * 8;       // 32 * 8

    const int cta = blockIdx.x;
    const int tid = threadIdx.x;
    const int c0  = (cta >> 1) * 8;      // column base
    const int b0  = (cta & 1) * BROWS;   // batch base

    // resident weights: 24 columns of 512
    for (int i = tid; i < 24 * INF; i += TPB) {
        int j = i >> 9;
        int k = i & (INF - 1);
        float v;
        if (j < 8)       v = Wg[(size_t)(INF + k) * NGATE + c0 + j];
        else if (j < 16) v = Wg[(size_t)(INF + k) * NGATE + H + c0 + (j - 8)];
        else             v = Wc[(size_t)(INF + k) * H + c0 + (j - 16)];
        sW[j * WST + k] = v;
    }
    __syncthreads();

    // phase1 mapping: cg in [0,4), bg in [0,8), ks1 in [0,16) of 32 K
    const int cg  = tid & 3;
    const int bg1 = (tid >> 2) & 7;
    const int k1  = (tid >> 5) * 32;
    // phase2 mapping: cg2 in [0,2), bg2 in [0,8), ks2 in [0,32) of 16 K
    const int cg2 = tid & 1;
    const int bg2 = (tid >> 1) & 7;
    const int k2  = (tid >> 4) * 16;

    // phase1 reduction: 1 output/thread. c1 in [0,16), b1 in [0,32)
    const int c1 = tid >> 5, b1 = tid & 31;
    const int gcol = (c1 < 8) ? (c0 + c1) : (H + c0 + (c1 - 8));
    // phase2 reduction: threads < 256
    const int c2o = tid >> 5, b2o = tid & 31;

    for (int t = 0; t < SEQ; t++) {
        const size_t xbase = (size_t)t * BATCH * NTOT;
        // prefetch x-projection for my gate output
        float xg = __ldg(g_xproj + xbase + (size_t)(b0 + b1) * NTOT + gcol);

        // ---- stage h rows [b0, b0+32) ----
#pragma unroll
        for (int n = 0; n < 8; n++) {
            int i = tid + n * 512;            // 0..4095 float4 slots
            int row = i >> 7;
            int cc  = (i & 127) * 4;
            *(float4*)(sh + row * WST + cc) =
                __ldcg((const float4*)(g_h + (size_t)(b0 + row) * H + cc));
        }
        __syncthreads();

        // ---- phase 1 main: cols cg+4i, batches bg1+8j, K slice k1 ----
        {
            float acc[4][4];
#pragma unroll
            for (int i = 0; i < 4; i++)
#pragma unroll
                for (int j = 0; j < 4; j++) acc[i][j] = 0.f;

            const float* w0 = sW + (cg + 0)  * WST + k1;
            const float* w1 = sW + (cg + 4)  * WST + k1;
            const float* w2 = sW + (cg + 8)  * WST + k1;
            const float* w3 = sW + (cg + 12) * WST + k1;
            const float* h0p = sh + (bg1 + 0)  * WST + k1;
            const float* h1p = sh + (bg1 + 8)  * WST + k1;
            const float* h2p = sh + (bg1 + 16) * WST + k1;
            const float* h3p = sh + (bg1 + 24) * WST + k1;

#pragma unroll
            for (int kk = 0; kk < 32; kk += 4) {
                float4 w[4], h[4];
                w[0] = *(const float4*)(w0 + kk);
                w[1] = *(const float4*)(w1 + kk);
                w[2] = *(const float4*)(w2 + kk);
                w[3] = *(const float4*)(w3 + kk);
                h[0] = *(const float4*)(h0p + kk);
                h[1] = *(const float4*)(h1p + kk);
                h[2] = *(const float4*)(h2p + kk);
                h[3] = *(const float4*)(h3p + kk);
#pragma unroll
                for (int i = 0; i < 4; i++)
#pragma unroll
                    for (int j = 0; j < 4; j++)
                        acc[i][j] += w[i].x * h[j].x + w[i].y * h[j].y +
                                     w[i].z * h[j].z + w[i].w * h[j].w;
            }
            const int ks1 = tid >> 5;
            float* pb = sPart + ks1 * P1SL;
#pragma unroll
            for (int i = 0; i < 4; i++)
#pragma unroll
                for (int j = 0; j < 4; j++)
                    pb[(cg + 4 * i) * CSTR + (bg1 + 8 * j)] = acc[i][j];
        }
        __syncthreads();

        // ---- phase 1 reduction + activation (1 output/thread) ----
        {
            float s = xg;
#pragma unroll
            for (int q = 0; q < 16; q++)
                s += sPart[q * P1SL + c1 * CSTR + b1];
            float sig = 1.f / (1.f + expf(-s));
            if (c1 < 8) {
                sZ[b1 * 8 + c1] = sig;
            } else {
                int cc = c1 - 8;
                g_rh[(size_t)(b0 + b1) * H + c0 + cc] =
                    sig * sh[b1 * WST + c0 + cc];
            }
        }
        // stash old h for my cand cols (sh gets overwritten by rh)
        if (tid < BROWS * 8) {
            int b = tid >> 3, c = tid & 7;
            sHold[tid] = sh[b * WST + c0 + c];
        }
        grid_barrier();   // publish g_rh

        // prefetch cand x-projection
        float xc = 0.f;
        if (tid < 256)
            xc = __ldg(g_xproj + xbase + (size_t)(b0 + b2o) * NTOT + NGATE + c0 + c2o);

        // ---- stage rh rows [b0, b0+32) ----
#pragma unroll
        for (int n = 0; n < 8; n++) {
            int i = tid + n * 512;
            int row = i >> 7;
            int cc  = (i & 127) * 4;
            *(float4*)(sh + row * WST + cc) =
                __ldcg((const float4*)(g_rh + (size_t)(b0 + row) * H + cc));
        }
        __syncthreads();

        // ---- phase 2 main: cols cg2+2i, batches bg2+8j, K slice k2 ----
        {
            float acc[4][4];
#pragma unroll
            for (int i = 0; i < 4; i++)
#pragma unroll
                for (int j = 0; j < 4; j++) acc[i][j] = 0.f;

            const float* w0 = sW + (16 + cg2 + 0) * WST + k2;
            const float* w1 = sW + (16 + cg2 + 2) * WST + k2;
            const float* w2 = sW + (16 + cg2 + 4) * WST + k2;
            const float* w3 = sW + (16 + cg2 + 6) * WST + k2;
            const float* r0p = sh + (bg2 + 0)  * WST + k2;
            const float* r1p = sh + (bg2 + 8)  * WST + k2;
            const float* r2p = sh + (bg2 + 16) * WST + k2;
            const float* r3p = sh + (bg2 + 24) * WST + k2;

#pragma unroll
            for (int kk = 0; kk < 16; kk += 4) {
                float4 w[4], h[4];
                w[0] = *(const float4*)(w0 + kk);
                w[1] = *(const float4*)(w1 + kk);
                w[2] = *(const float4*)(w2 + kk);
                w[3] = *(const float4*)(w3 + kk);
                h[0] = *(const float4*)(r0p + kk);
                h[1] = *(const float4*)(r1p + kk);
                h[2] = *(const float4*)(r2p + kk);
                h[3] = *(const float4*)(r3p + kk);
#pragma unroll
                for (int i = 0; i < 4; i++)
#pragma unroll
                    for (int j = 0; j < 4; j++)
                        acc[i][j] += w[i].x * h[j].x + w[i].y * h[j].y +
                                     w[i].z * h[j].z + w[i].w * h[j].w;
            }
            const int ks2 = tid >> 4;
            float* pb = sPart + ks2 * P2SL;
#pragma unroll
            for (int i = 0; i < 4; i++)
#pragma unroll
                for (int j = 0; j < 4; j++)
                    pb[(cg2 + 2 * i) * CSTR + (bg2 + 8 * j)] = acc[i][j];
        }
        __syncthreads();

        // ---- phase 2 reduction + h update (threads < 256) ----
        if (tid < 256) {
            float sum = xc;
#pragma unroll
            for (int q = 0; q < 32; q++)
                sum += sPart[q * P2SL + c2o * CSTR + b2o];
            float cand = tanhf(sum);
            float hold = sHold[b2o * 8 + c2o];
            float z    = sZ[b2o * 8 + c2o];
            float hn   = hold + z * (cand - hold);
            int gb = b0 + b2o;
            g_h[(size_t)gb * H + c0 + c2o] = hn;
            out[((size_t)t * BATCH + gb) * H + c0 + c2o] = hn;
            if (write_hlast && t == SEQ - 1)
                out[(size_t)SEQ * BATCH * H + (size_t)gb * H + c0 + c2o] = hn;
        }
        grid_barrier();   // publish g_h for next step
    }
}

// ---------------------------------------------------------------------------
// Launch
// ---------------------------------------------------------------------------
extern "C" void kernel_launch(void* const* d_in, const int* in_sizes, int n_in,
                              void* d_out, int out_size) {
    const float* x  = (const float*)d_in[0];
    const float* h0 = (const float*)d_in[1];
    const float* Wg = (const float*)d_in[2];
    const float* bg = (const float*)d_in[3];
    const float* Wc = (const float*)d_in[4];
    const float* bc = (const float*)d_in[5];
    float* out = (float*)d_out;

    (void)in_sizes; (void)n_in;

    dim3 g1(NTOT / XBN, (SEQ * BATCH) / XBM);
    xproj_kernel<<<g1, 256>>>(x, Wg, bg, Wc, bc);

    init_h_kernel<<<(BATCH * H + 255) / 256, 256>>>(h0);

    const int smem_bytes =
        (24 * WST + BROWS * WST + 10752 + BROWS * 8 * 2) * (int)sizeof(float);
    cudaFuncSetAttribute(gru_persistent_kernel,
                         cudaFuncAttributeMaxDynamicSharedMemorySize, smem_bytes);
    int write_hlast = (out_size >= SEQ * BATCH * H + BATCH * H) ? 1 : 0;
    gru_persistent_kernel<<<G, TPB, smem_bytes>>>(Wg, Wc, out, write_hlast);
}

// round 12
// speedup vs baseline: 2.3176x; 1.1522x over previous
#include <cuda_runtime.h>
#include <math.h>
#include <stdint.h>
#include <stddef.h>

// Problem constants
#define SEQ   2048
#define BATCH 64
#define INF   512
#define H     512
#define NGATE 1024
#define NTOT  1536

// Recurrence config: 128 CTAs = 64 col-groups x 2 batch-halves
#define G      128
#define TPB    512
#define WST    516     // padded smem row stride (floats)
#define BROWS  32      // batches per CTA

// split-K partial layout
#define CSTR   40
#define P1SL   640     // 16 cols * 40
#define P2SL   336     // 8 cols * 40 + pad

// ---------------------------------------------------------------------------
// Scratch
// ---------------------------------------------------------------------------
__device__ float g_xproj[(size_t)SEQ * BATCH * NTOT];
__device__ float g_h[BATCH * H];
__device__ float g_rh[BATCH * H];
__device__ unsigned int g_bar_count;
__device__ unsigned int g_bar_gen;

// ---------------------------------------------------------------------------
// tf32 helpers
// ---------------------------------------------------------------------------
__device__ __forceinline__ float totf(float x) {
    uint32_t u;
    asm("cvt.rna.tf32.f32 %0, %1;" : "=r"(u) : "f"(x));
    return __uint_as_float(u);
}

__device__ __forceinline__ void mma_tf32(float& d0, float& d1, float& d2, float& d3,
                                         uint32_t a0, uint32_t a1, uint32_t a2, uint32_t a3,
                                         uint32_t b0, uint32_t b1) {
    asm volatile(
        "mma.sync.aligned.m16n8k8.row.col.f32.tf32.tf32.f32 "
        "{%0,%1,%2,%3}, {%4,%5,%6,%7}, {%8,%9}, {%0,%1,%2,%3};\n"
        : "+f"(d0), "+f"(d1), "+f"(d2), "+f"(d3)
        : "r"(a0), "r"(a1), "r"(a2), "r"(a3), "r"(b0), "r"(b1));
}

// ---------------------------------------------------------------------------
// Kernel 1: projection GEMM (unchanged — proven, fma 70.6%)
// ---------------------------------------------------------------------------
#define XBM 128
#define XBN 128
#define XBK 8

__global__ void __launch_bounds__(256, 2)
xproj_kernel(const float* __restrict__ X,
             const float* __restrict__ Wg,
             const float* __restrict__ bg,
             const float* __restrict__ Wc,
             const float* __restrict__ bc) {
    __shared__ float As[XBK][XBM + 4];
    __shared__ float Bs[XBK][XBN + 4];

    const int tid = threadIdx.x;
    const int n0  = blockIdx.x * XBN;
    const size_t m0 = (size_t)blockIdx.y * XBM;

    const bool is_gate = (n0 < NGATE);
    const float* Bbase = is_gate ? (Wg + n0) : (Wc + (n0 - NGATE));
    const int    ldB   = is_gate ? NGATE : H;
    const float* bias  = is_gate ? (bg + n0) : (bc + (n0 - NGATE));

    const int am = tid >> 1;
    const int ak = (tid & 1) * 4;
    const int br = tid >> 5;
    const int bn = (tid & 31) * 4;

    const int tm4 = (tid >> 4) * 4;
    const int tn4 = (tid & 15) * 4;

    float acc[8][8];
#pragma unroll
    for (int i = 0; i < 8; i++)
#pragma unroll
        for (int j = 0; j < 8; j++) acc[i][j] = 0.f;

    float4 av = *(const float4*)(X + (m0 + am) * INF + ak);
    float4 bv = *(const float4*)(Bbase + (size_t)br * ldB + bn);

    for (int k0 = 0; k0 < INF; k0 += XBK) {
        As[ak + 0][am] = av.x;
        As[ak + 1][am] = av.y;
        As[ak + 2][am] = av.z;
        As[ak + 3][am] = av.w;
        *(float4*)&Bs[br][bn] = bv;
        __syncthreads();

        if (k0 + XBK < INF) {
            av = *(const float4*)(X + (m0 + am) * INF + k0 + XBK + ak);
            bv = *(const float4*)(Bbase + (size_t)(k0 + XBK + br) * ldB + bn);
        }

#pragma unroll
        for (int k = 0; k < XBK; k++) {
            float4 a0 = *(float4*)&As[k][tm4];
            float4 a1 = *(float4*)&As[k][64 + tm4];
            float4 b0 = *(float4*)&Bs[k][tn4];
            float4 b1 = *(float4*)&Bs[k][64 + tn4];
            float af[8] = {a0.x, a0.y, a0.z, a0.w, a1.x, a1.y, a1.z, a1.w};
            float bf[8] = {b0.x, b0.y, b0.z, b0.w, b1.x, b1.y, b1.z, b1.w};
#pragma unroll
            for (int i = 0; i < 8; i++)
#pragma unroll
                for (int j = 0; j < 8; j++)
                    acc[i][j] += af[i] * bf[j];
        }
        __syncthreads();
    }

    const float4 bv0 = *(const float4*)(bias + tn4);
    const float4 bv1 = *(const float4*)(bias + 64 + tn4);
    const float bb[8] = {bv0.x, bv0.y, bv0.z, bv0.w, bv1.x, bv1.y, bv1.z, bv1.w};
#pragma unroll
    for (int i = 0; i < 8; i++) {
        const size_t row = m0 + ((i < 4) ? (tm4 + i) : (64 + tm4 + i - 4));
        float4 o0, o1;
        o0.x = acc[i][0] + bb[0]; o0.y = acc[i][1] + bb[1];
        o0.z = acc[i][2] + bb[2]; o0.w = acc[i][3] + bb[3];
        o1.x = acc[i][4] + bb[4]; o1.y = acc[i][5] + bb[5];
        o1.z = acc[i][6] + bb[6]; o1.w = acc[i][7] + bb[7];
        float* orow = g_xproj + row * NTOT + n0;
        *(float4*)(orow + tn4)      = o0;
        *(float4*)(orow + 64 + tn4) = o1;
    }
}

// ---------------------------------------------------------------------------
// h0 -> g_h
// ---------------------------------------------------------------------------
__global__ void init_h_kernel(const float* __restrict__ h0) {
    int i = blockIdx.x * blockDim.x + threadIdx.x;
    if (i < BATCH * H) g_h[i] = h0[i];
}

// ---------------------------------------------------------------------------
// Software grid barrier (proven form)
// ---------------------------------------------------------------------------
__device__ __forceinline__ void grid_barrier() {
    __threadfence();
    __syncthreads();
    if (threadIdx.x == 0) {
        unsigned int gen = *(volatile unsigned int*)&g_bar_gen;
        unsigned int a = atomicAdd(&g_bar_count, 1u);
        if (a == G - 1) {
            atomicExch(&g_bar_count, 0u);
            __threadfence();
            atomicAdd(&g_bar_gen, 1u);
        } else {
            while (*(volatile unsigned int*)&g_bar_gen == gen) { }
        }
    }
    __syncthreads();
}

// ---------------------------------------------------------------------------
// Kernel 2: persistent GRU recurrence, tf32 tensor-core GEMMs.
//   CTA i: col-group (i>>1)*8, batch half (i&1)*32.
//   Phase1: C[32b x 16c] via 16 warps = 2(M16) x 2(N8) x 4(K128), 16 mma each.
//   Phase2: C[32b x  8c] via 16 warps = 2(M16) x 1(N8) x 8(K64),   8 mma each.
//   Operands staged as tf32; state path (hold/rh/out) stays exact fp32 (sHF).
// ---------------------------------------------------------------------------
__global__ void __launch_bounds__(TPB, 1)
gru_persistent_kernel(const float* __restrict__ Wg,
                      const float* __restrict__ Wc,
                      float* __restrict__ out,
                      int write_hlast) {
    extern __shared__ float smem[];
    float* sW    = smem;                 // 24 cols * WST, tf32 (z:0-7 r:8-15 c:16-23)
    float* sh    = sW + 24 * WST;        // 32 rows * WST, tf32 (h, then rh)
    float* sPart = sh + BROWS * WST;     // max(4*P1SL, 8*P2SL) = 2688
    float* sZ    = sPart + 2688;         // 32 * 8
    float* sHF   = sZ + BROWS * 8;       // 32 * 8 exact fp32 h (own cols)

    const int cta = blockIdx.x;
    const int tid = threadIdx.x;
    const int c0  = (cta >> 1) * 8;      // column base
    const int b0  = (cta & 1) * BROWS;   // batch base

    const int lane = tid & 31;
    const int wrp  = tid >> 5;
    const int grp  = lane >> 2;          // 0..7
    const int tig  = lane & 3;           // 0..3

    // resident weights (tf32-rounded): 24 columns of 512
    for (int i = tid; i < 24 * INF; i += TPB) {
        int j = i >> 9;
        int k = i & (INF - 1);
        float v;
        if (j < 8)       v = Wg[(size_t)(INF + k) * NGATE + c0 + j];
        else if (j < 16) v = Wg[(size_t)(INF + k) * NGATE + H + c0 + (j - 8)];
        else             v = Wc[(size_t)(INF + k) * H + c0 + (j - 16)];
        sW[j * WST + k] = totf(v);
    }
    __syncthreads();

    // phase1 warp job: mt1 (M-tile), nt1 (N-tile), kr1 (K-range of 128)
    const int mt1 = wrp & 1, nt1 = (wrp >> 1) & 1, kr1 = wrp >> 2;
    const float* aB1 = sh + (mt1 * 16 + grp) * WST + kr1 * 128 + tig;
    const float* bB1 = sW + (nt1 * 8 + grp) * WST + kr1 * 128 + tig;
    // phase2 warp job: mt2, kr2 (K-range of 64)
    const int mt2 = wrp & 1, kr2 = wrp >> 1;
    const float* aB2 = sh + (mt2 * 16 + grp) * WST + kr2 * 64 + tig;
    const float* bB2 = sW + (16 + grp) * WST + kr2 * 64 + tig;

    // D-fragment output coordinates (shared by both phases)
    const int fcol = tig * 2;            // local col of d0; d1 = +1
    const int fbat1 = mt1 * 16 + grp;    // local batch of d0/d1; d2/d3 = +8

    // phase1 reduction: 1 output/thread
    const int c1 = tid >> 5, b1 = tid & 31;
    const int gcol = (c1 < 8) ? (c0 + c1) : (H + c0 + (c1 - 8));
    // phase2 reduction: threads < 256
    const int c2o = tid >> 5, b2o = tid & 31;

    for (int t = 0; t < SEQ; t++) {
        const size_t xbase = (size_t)t * BATCH * NTOT;
        float xg = __ldg(g_xproj + xbase + (size_t)(b0 + b1) * NTOT + gcol);

        // ---- stage h rows [b0, b0+32): tf32 into sh, exact fp32 own-cols ----
#pragma unroll
        for (int n = 0; n < 8; n++) {
            int i = tid + n * 512;
            int row = i >> 7;
            int cc  = (i & 127) * 4;
            float4 v = __ldcg((const float4*)(g_h + (size_t)(b0 + row) * H + cc));
            v.x = totf(v.x); v.y = totf(v.y); v.z = totf(v.z); v.w = totf(v.w);
            *(float4*)(sh + row * WST + cc) = v;
        }
        if (tid < BROWS * 8) {
            int b = tid >> 3, c = tid & 7;
            sHF[tid] = __ldcg(g_h + (size_t)(b0 + b) * H + c0 + c);
        }
        __syncthreads();

        // ---- phase 1: gate GEMM via mma ----
        {
            float d0 = 0.f, d1 = 0.f, d2 = 0.f, d3 = 0.f;
#pragma unroll
            for (int ks = 0; ks < 16; ks++) {
                const int off = ks * 8;
                uint32_t a0 = __float_as_uint(aB1[off]);
                uint32_t a1 = __float_as_uint(aB1[8 * WST + off]);
                uint32_t a2 = __float_as_uint(aB1[off + 4]);
                uint32_t a3 = __float_as_uint(aB1[8 * WST + off + 4]);
                uint32_t b0r = __float_as_uint(bB1[off]);
                uint32_t b1r = __float_as_uint(bB1[off + 4]);
                mma_tf32(d0, d1, d2, d3, a0, a1, a2, a3, b0r, b1r);
            }
            float* pb = sPart + kr1 * P1SL;
            const int colL = nt1 * 8 + fcol;
            pb[(colL + 0) * CSTR + fbat1]     = d0;
            pb[(colL + 1) * CSTR + fbat1]     = d1;
            pb[(colL + 0) * CSTR + fbat1 + 8] = d2;
            pb[(colL + 1) * CSTR + fbat1 + 8] = d3;
        }
        __syncthreads();

        // ---- phase 1 reduction + activation ----
        {
            float s = xg;
#pragma unroll
            for (int q = 0; q < 4; q++)
                s += sPart[q * P1SL + c1 * CSTR + b1];
            float sig = 1.f / (1.f + expf(-s));
            if (c1 < 8) {
                sZ[b1 * 8 + c1] = sig;
            } else {
                int cc = c1 - 8;
                g_rh[(size_t)(b0 + b1) * H + c0 + cc] = sig * sHF[b1 * 8 + cc];
            }
        }
        grid_barrier();   // publish g_rh

        // prefetch cand x-projection
        float xc = 0.f;
        if (tid < 256)
            xc = __ldg(g_xproj + xbase + (size_t)(b0 + b2o) * NTOT + NGATE + c0 + c2o);

        // ---- stage rh rows [b0, b0+32) as tf32 ----
#pragma unroll
        for (int n = 0; n < 8; n++) {
            int i = tid + n * 512;
            int row = i >> 7;
            int cc  = (i & 127) * 4;
            float4 v = __ldcg((const float4*)(g_rh + (size_t)(b0 + row) * H + cc));
            v.x = totf(v.x); v.y = totf(v.y); v.z = totf(v.z); v.w = totf(v.w);
            *(float4*)(sh + row * WST + cc) = v;
        }
        __syncthreads();

        // ---- phase 2: candidate GEMM via mma ----
        {
            float d0 = 0.f, d1 = 0.f, d2 = 0.f, d3 = 0.f;
#pragma unroll
            for (int ks = 0; ks < 8; ks++) {
                const int off = ks * 8;
                uint32_t a0 = __float_as_uint(aB2[off]);
                uint32_t a1 = __float_as_uint(aB2[8 * WST + off]);
                uint32_t a2 = __float_as_uint(aB2[off + 4]);
                uint32_t a3 = __float_as_uint(aB2[8 * WST + off + 4]);
                uint32_t b0r = __float_as_uint(bB2[off]);
                uint32_t b1r = __float_as_uint(bB2[off + 4]);
                mma_tf32(d0, d1, d2, d3, a0, a1, a2, a3, b0r, b1r);
            }
            float* pb = sPart + kr2 * P2SL;
            const int fbat2 = mt2 * 16 + grp;
            pb[(fcol + 0) * CSTR + fbat2]     = d0;
            pb[(fcol + 1) * CSTR + fbat2]     = d1;
            pb[(fcol + 0) * CSTR + fbat2 + 8] = d2;
            pb[(fcol + 1) * CSTR + fbat2 + 8] = d3;
        }
        __syncthreads();

        // ---- phase 2 reduction + h update (threads < 256) ----
        if (tid < 256) {
            float sum = xc;
#pragma unroll
            for (int q = 0; q < 8; q++)
                sum += sPart[q * P2SL + c2o * CSTR + b2o];
            float cand = tanhf(sum);
            float hold = sHF[b2o * 8 + c2o];
            float z    = sZ[b2o * 8 + c2o];
            float hn   = hold + z * (cand - hold);
            int gb = b0 + b2o;
            g_h[(size_t)gb * H + c0 + c2o] = hn;
            out[((size_t)t * BATCH + gb) * H + c0 + c2o] = hn;
            if (write_hlast && t == SEQ - 1)
                out[(size_t)SEQ * BATCH * H + (size_t)gb * H + c0 + c2o] = hn;
        }
        grid_barrier();   // publish g_h for next step
    }
}

// ---------------------------------------------------------------------------
// Launch
// ---------------------------------------------------------------------------
extern "C" void kernel_launch(void* const* d_in, const int* in_sizes, int n_in,
                              void* d_out, int out_size) {
    const float* x  = (const float*)d_in[0];
    const float* h0 = (const float*)d_in[1];
    const float* Wg = (const float*)d_in[2];
    const float* bg = (const float*)d_in[3];
    const float* Wc = (const float*)d_in[4];
    const float* bc = (const float*)d_in[5];
    float* out = (float*)d_out;

    (void)in_sizes; (void)n_in;

    dim3 g1(NTOT / XBN, (SEQ * BATCH) / XBM);
    xproj_kernel<<<g1, 256>>>(x, Wg, bg, Wc, bc);

    init_h_kernel<<<(BATCH * H + 255) / 256, 256>>>(h0);

    const int smem_bytes =
        (24 * WST + BROWS * WST + 2688 + BROWS * 8 * 2) * (int)sizeof(float);
    cudaFuncSetAttribute(gru_persistent_kernel,
                         cudaFuncAttributeMaxDynamicSharedMemorySize, smem_bytes);
    int write_hlast = (out_size >= SEQ * BATCH * H + BATCH * H) ? 1 : 0;
    gru_persistent_kernel<<<G, TPB, smem_bytes>>>(Wg, Wc, out, write_hlast);
}

// round 13
// speedup vs baseline: 2.4017x; 1.0363x over previous
#include <cuda_runtime.h>
#include <math.h>
#include <stdint.h>
#include <stddef.h>

// Problem constants
#define SEQ   2048
#define BATCH 64
#define INF   512
#define H     512
#define NGATE 1024
#define NTOT  1536

// Recurrence config: 128 CTAs = 64 col-groups x 2 batch-halves
#define G      128
#define TPB    512
#define WST    516     // padded smem row stride (floats)
#define BROWS  32      // batches per CTA

// split-K partial layout
#define CSTR   40
#define P1SL   640     // 16 cols * 40
#define P2SL   336     // 8 cols * 40 + pad

// ---------------------------------------------------------------------------
// Scratch
// ---------------------------------------------------------------------------
__device__ float g_xproj[(size_t)SEQ * BATCH * NTOT];
__device__ float g_h[BATCH * H];
__device__ float g_rh[BATCH * H];
__device__ unsigned int g_bar_count;
__device__ unsigned int g_bar_gen;

// ---------------------------------------------------------------------------
// tf32 helpers
// ---------------------------------------------------------------------------
__device__ __forceinline__ float totf(float x) {
    uint32_t u;
    asm("cvt.rna.tf32.f32 %0, %1;" : "=r"(u) : "f"(x));
    return __uint_as_float(u);
}

__device__ __forceinline__ void mma_tf32(float& d0, float& d1, float& d2, float& d3,
                                         uint32_t a0, uint32_t a1, uint32_t a2, uint32_t a3,
                                         uint32_t b0, uint32_t b1) {
    asm volatile(
        "mma.sync.aligned.m16n8k8.row.col.f32.tf32.tf32.f32 "
        "{%0,%1,%2,%3}, {%4,%5,%6,%7}, {%8,%9}, {%0,%1,%2,%3};\n"
        : "+f"(d0), "+f"(d1), "+f"(d2), "+f"(d3)
        : "r"(a0), "r"(a1), "r"(a2), "r"(a3), "r"(b0), "r"(b1));
}

// ---------------------------------------------------------------------------
// Kernel 1: tf32 tensor-core projection GEMM.
//   P[m, n] = X[m,:] @ W[:, n] + bias[n]
//   CTA tile 128x128, K-chunks of 16. 8 warps as 2(m) x 4(n), warp tile 64x32,
//   16 m16n8k8 fragments per warp. Fragment indexing identical to the proven
//   recurrence mma scheme. KC=20 pad -> conflict-free fragment loads.
// ---------------------------------------------------------------------------
#define KC 20

__global__ void __launch_bounds__(256, 2)
xproj_kernel(const float* __restrict__ X,
             const float* __restrict__ Wg,
             const float* __restrict__ bg,
             const float* __restrict__ Wc,
             const float* __restrict__ bc) {
    __shared__ float As[128 * KC];   // A[m][k], m-major
    __shared__ float Bs[128 * KC];   // B[n][k], n-major

    const int tid = threadIdx.x;
    const int n0  = blockIdx.x * 128;
    const size_t m0 = (size_t)blockIdx.y * 128;

    const bool is_gate = (n0 < NGATE);
    const float* Bbase = is_gate ? (Wg + n0) : (Wc + (n0 - NGATE));
    const int    ldB   = is_gate ? NGATE : H;
    const float* bias  = is_gate ? (bg + n0) : (bc + (n0 - NGATE));

    const int lane = tid & 31;
    const int wrp  = tid >> 5;
    const int grp  = lane >> 2;     // 0..7
    const int tig  = lane & 3;      // 0..3
    const int m0w  = (wrp & 1) * 64;
    const int n0w  = (wrp >> 1) * 32;

    // global load mapping (2 float4 each for A and B per chunk)
    const int amA[2] = { tid >> 2, (tid + 256) >> 2 };         // 0..127
    const int akA    = (tid & 3) * 4;                          // 0,4,8,12
    const int bkB[2] = { tid >> 5, (tid >> 5) + 8 };           // 0..15
    const int bnB    = (tid & 31) * 4;                         // 0..124

    float acc[4][4][4];
#pragma unroll
    for (int mi = 0; mi < 4; mi++)
#pragma unroll
        for (int ni = 0; ni < 4; ni++)
#pragma unroll
            for (int r = 0; r < 4; r++) acc[mi][ni][r] = 0.f;

    float4 aR[2], bR[2];
#pragma unroll
    for (int r = 0; r < 2; r++) {
        aR[r] = *(const float4*)(X + (m0 + amA[r]) * INF + akA);
        bR[r] = *(const float4*)(Bbase + (size_t)bkB[r] * ldB + bnB);
    }

#pragma unroll 1
    for (int kc = 0; kc < INF / 16; kc++) {
        // store staged tiles (tf32-rounded)
#pragma unroll
        for (int r = 0; r < 2; r++) {
            float* ap = As + amA[r] * KC + akA;
            ap[0] = totf(aR[r].x); ap[1] = totf(aR[r].y);
            ap[2] = totf(aR[r].z); ap[3] = totf(aR[r].w);
            Bs[(bnB + 0) * KC + bkB[r]] = totf(bR[r].x);
            Bs[(bnB + 1) * KC + bkB[r]] = totf(bR[r].y);
            Bs[(bnB + 2) * KC + bkB[r]] = totf(bR[r].z);
            Bs[(bnB + 3) * KC + bkB[r]] = totf(bR[r].w);
        }
        __syncthreads();

        if (kc + 1 < INF / 16) {
            const int k0 = (kc + 1) * 16;
#pragma unroll
            for (int r = 0; r < 2; r++) {
                aR[r] = *(const float4*)(X + (m0 + amA[r]) * INF + k0 + akA);
                bR[r] = *(const float4*)(Bbase + (size_t)(k0 + bkB[r]) * ldB + bnB);
            }
        }

#pragma unroll
        for (int kk = 0; kk < 16; kk += 8) {
            uint32_t af[4][4], bf[4][2];
#pragma unroll
            for (int mi = 0; mi < 4; mi++) {
                const float* ap = As + (m0w + mi * 16 + grp) * KC + kk + tig;
                af[mi][0] = __float_as_uint(ap[0]);
                af[mi][1] = __float_as_uint(ap[8 * KC]);
                af[mi][2] = __float_as_uint(ap[4]);
                af[mi][3] = __float_as_uint(ap[8 * KC + 4]);
            }
#pragma unroll
            for (int ni = 0; ni < 4; ni++) {
                const float* bp = Bs + (n0w + ni * 8 + grp) * KC + kk + tig;
                bf[ni][0] = __float_as_uint(bp[0]);
                bf[ni][1] = __float_as_uint(bp[4]);
            }
#pragma unroll
            for (int mi = 0; mi < 4; mi++)
#pragma unroll
                for (int ni = 0; ni < 4; ni++)
                    mma_tf32(acc[mi][ni][0], acc[mi][ni][1],
                             acc[mi][ni][2], acc[mi][ni][3],
                             af[mi][0], af[mi][1], af[mi][2], af[mi][3],
                             bf[ni][0], bf[ni][1]);
        }
        __syncthreads();
    }

    // epilogue: bias + store
#pragma unroll
    for (int ni = 0; ni < 4; ni++) {
        const int cl = n0w + ni * 8 + 2 * tig;          // local col of d0
        const float bz0 = bias[cl];
        const float bz1 = bias[cl + 1];
#pragma unroll
        for (int mi = 0; mi < 4; mi++) {
            const size_t r0 = m0 + m0w + mi * 16 + grp;
            float2 v0 = { acc[mi][ni][0] + bz0, acc[mi][ni][1] + bz1 };
            float2 v1 = { acc[mi][ni][2] + bz0, acc[mi][ni][3] + bz1 };
            *(float2*)(g_xproj + r0 * NTOT + n0 + cl)       = v0;
            *(float2*)(g_xproj + (r0 + 8) * NTOT + n0 + cl) = v1;
        }
    }
}

// ---------------------------------------------------------------------------
// h0 -> g_h
// ---------------------------------------------------------------------------
__global__ void init_h_kernel(const float* __restrict__ h0) {
    int i = blockIdx.x * blockDim.x + threadIdx.x;
    if (i < BATCH * H) g_h[i] = h0[i];
}

// ---------------------------------------------------------------------------
// Software grid barrier (proven form)
// ---------------------------------------------------------------------------
__device__ __forceinline__ void grid_barrier() {
    __threadfence();
    __syncthreads();
    if (threadIdx.x == 0) {
        unsigned int gen = *(volatile unsigned int*)&g_bar_gen;
        unsigned int a = atomicAdd(&g_bar_count, 1u);
        if (a == G - 1) {
            atomicExch(&g_bar_count, 0u);
            __threadfence();
            atomicAdd(&g_bar_gen, 1u);
        } else {
            while (*(volatile unsigned int*)&g_bar_gen == gen) { }
        }
    }
    __syncthreads();
}

// ---------------------------------------------------------------------------
// Kernel 2: persistent GRU recurrence (unchanged from round 12 — proven)
// ---------------------------------------------------------------------------
__global__ void __launch_bounds__(TPB, 1)
gru_persistent_kernel(const float* __restrict__ Wg,
                      const float* __restrict__ Wc,
                      float* __restrict__ out,
                      int write_hlast) {
    extern __shared__ float smem[];
    float* sW    = smem;                 // 24 cols * WST, tf32
    float* sh    = sW + 24 * WST;        // 32 rows * WST, tf32 (h, then rh)
    float* sPart = sh + BROWS * WST;     // 2688
    float* sZ    = sPart + 2688;         // 32 * 8
    float* sHF   = sZ + BROWS * 8;       // 32 * 8 exact fp32 h (own cols)

    const int cta = blockIdx.x;
    const int tid = threadIdx.x;
    const int c0  = (cta >> 1) * 8;
    const int b0  = (cta & 1) * BROWS;

    const int lane = tid & 31;
    const int wrp  = tid >> 5;
    const int grp  = lane >> 2;
    const int tig  = lane & 3;

    for (int i = tid; i < 24 * INF; i += TPB) {
        int j = i >> 9;
        int k = i & (INF - 1);
        float v;
        if (j < 8)       v = Wg[(size_t)(INF + k) * NGATE + c0 + j];
        else if (j < 16) v = Wg[(size_t)(INF + k) * NGATE + H + c0 + (j - 8)];
        else             v = Wc[(size_t)(INF + k) * H + c0 + (j - 16)];
        sW[j * WST + k] = totf(v);
    }
    __syncthreads();

    const int mt1 = wrp & 1, nt1 = (wrp >> 1) & 1, kr1 = wrp >> 2;
    const float* aB1 = sh + (mt1 * 16 + grp) * WST + kr1 * 128 + tig;
    const float* bB1 = sW + (nt1 * 8 + grp) * WST + kr1 * 128 + tig;
    const int mt2 = wrp & 1, kr2 = wrp >> 1;
    const float* aB2 = sh + (mt2 * 16 + grp) * WST + kr2 * 64 + tig;
    const float* bB2 = sW + (16 + grp) * WST + kr2 * 64 + tig;

    const int fcol = tig * 2;
    const int fbat1 = mt1 * 16 + grp;

    const int c1 = tid >> 5, b1 = tid & 31;
    const int gcol = (c1 < 8) ? (c0 + c1) : (H + c0 + (c1 - 8));
    const int c2o = tid >> 5, b2o = tid & 31;

    for (int t = 0; t < SEQ; t++) {
        const size_t xbase = (size_t)t * BATCH * NTOT;
        float xg = __ldg(g_xproj + xbase + (size_t)(b0 + b1) * NTOT + gcol);

#pragma unroll
        for (int n = 0; n < 8; n++) {
            int i = tid + n * 512;
            int row = i >> 7;
            int cc  = (i & 127) * 4;
            float4 v = __ldcg((const float4*)(g_h + (size_t)(b0 + row) * H + cc));
            v.x = totf(v.x); v.y = totf(v.y); v.z = totf(v.z); v.w = totf(v.w);
            *(float4*)(sh + row * WST + cc) = v;
        }
        if (tid < BROWS * 8) {
            int b = tid >> 3, c = tid & 7;
            sHF[tid] = __ldcg(g_h + (size_t)(b0 + b) * H + c0 + c);
        }
        __syncthreads();

        {
            float d0 = 0.f, d1 = 0.f, d2 = 0.f, d3 = 0.f;
#pragma unroll
            for (int ks = 0; ks < 16; ks++) {
                const int off = ks * 8;
                uint32_t a0 = __float_as_uint(aB1[off]);
                uint32_t a1 = __float_as_uint(aB1[8 * WST + off]);
                uint32_t a2 = __float_as_uint(aB1[off + 4]);
                uint32_t a3 = __float_as_uint(aB1[8 * WST + off + 4]);
                uint32_t b0r = __float_as_uint(bB1[off]);
                uint32_t b1r = __float_as_uint(bB1[off + 4]);
                mma_tf32(d0, d1, d2, d3, a0, a1, a2, a3, b0r, b1r);
            }
            float* pb = sPart + kr1 * P1SL;
            const int colL = nt1 * 8 + fcol;
            pb[(colL + 0) * CSTR + fbat1]     = d0;
            pb[(colL + 1) * CSTR + fbat1]     = d1;
            pb[(colL + 0) * CSTR + fbat1 + 8] = d2;
            pb[(colL + 1) * CSTR + fbat1 + 8] = d3;
        }
        __syncthreads();

        {
            float s = xg;
#pragma unroll
            for (int q = 0; q < 4; q++)
                s += sPart[q * P1SL + c1 * CSTR + b1];
            float sig = 1.f / (1.f + expf(-s));
            if (c1 < 8) {
                sZ[b1 * 8 + c1] = sig;
            } else {
                int cc = c1 - 8;
                g_rh[(size_t)(b0 + b1) * H + c0 + cc] = sig * sHF[b1 * 8 + cc];
            }
        }
        grid_barrier();

        float xc = 0.f;
        if (tid < 256)
            xc = __ldg(g_xproj + xbase + (size_t)(b0 + b2o) * NTOT + NGATE + c0 + c2o);

#pragma unroll
        for (int n = 0; n < 8; n++) {
            int i = tid + n * 512;
            int row = i >> 7;
            int cc  = (i & 127) * 4;
            float4 v = __ldcg((const float4*)(g_rh + (size_t)(b0 + row) * H + cc));
            v.x = totf(v.x); v.y = totf(v.y); v.z = totf(v.z); v.w = totf(v.w);
            *(float4*)(sh + row * WST + cc) = v;
        }
        __syncthreads();

        {
            float d0 = 0.f, d1 = 0.f, d2 = 0.f, d3 = 0.f;
#pragma unroll
            for (int ks = 0; ks < 8; ks++) {
                const int off = ks * 8;
                uint32_t a0 = __float_as_uint(aB2[off]);
                uint32_t a1 = __float_as_uint(aB2[8 * WST + off]);
                uint32_t a2 = __float_as_uint(aB2[off + 4]);
                uint32_t a3 = __float_as_uint(aB2[8 * WST + off + 4]);
                uint32_t b0r = __float_as_uint(bB2[off]);
                uint32_t b1r = __float_as_uint(bB2[off + 4]);
                mma_tf32(d0, d1, d2, d3, a0, a1, a2, a3, b0r, b1r);
            }
            float* pb = sPart + kr2 * P2SL;
            const int fbat2 = mt2 * 16 + grp;
            pb[(fcol + 0) * CSTR + fbat2]     = d0;
            pb[(fcol + 1) * CSTR + fbat2]     = d1;
            pb[(fcol + 0) * CSTR + fbat2 + 8] = d2;
            pb[(fcol + 1) * CSTR + fbat2 + 8] = d3;
        }
        __syncthreads();

        if (tid < 256) {
            float sum = xc;
#pragma unroll
            for (int q = 0; q < 8; q++)
                sum += sPart[q * P2SL + c2o * CSTR + b2o];
            float cand = tanhf(sum);
            float hold = sHF[b2o * 8 + c2o];
            float z    = sZ[b2o * 8 + c2o];
            float hn   = hold + z * (cand - hold);
            int gb = b0 + b2o;
            g_h[(size_t)gb * H + c0 + c2o] = hn;
            out[((size_t)t * BATCH + gb) * H + c0 + c2o] = hn;
            if (write_hlast && t == SEQ - 1)
                out[(size_t)SEQ * BATCH * H + (size_t)gb * H + c0 + c2o] = hn;
        }
        grid_barrier();
    }
}

// ---------------------------------------------------------------------------
// Launch
// ---------------------------------------------------------------------------
extern "C" void kernel_launch(void* const* d_in, const int* in_sizes, int n_in,
                              void* d_out, int out_size) {
    const float* x  = (const float*)d_in[0];
    const float* h0 = (const float*)d_in[1];
    const float* Wg = (const float*)d_in[2];
    const float* bg = (const float*)d_in[3];
    const float* Wc = (const float*)d_in[4];
    const float* bc = (const float*)d_in[5];
    float* out = (float*)d_out;

    (void)in_sizes; (void)n_in;

    dim3 g1(NTOT / 128, (SEQ * BATCH) / 128);
    xproj_kernel<<<g1, 256>>>(x, Wg, bg, Wc, bc);

    init_h_kernel<<<(BATCH * H + 255) / 256, 256>>>(h0);

    const int smem_bytes =
        (24 * WST + BROWS * WST + 2688 + BROWS * 8 * 2) * (int)sizeof(float);
    cudaFuncSetAttribute(gru_persistent_kernel,
                         cudaFuncAttributeMaxDynamicSharedMemorySize, smem_bytes);
    int write_hlast = (out_size >= SEQ * BATCH * H + BATCH * H) ? 1 : 0;
    gru_persistent_kernel<<<G, TPB, smem_bytes>>>(Wg, Wc, out, write_hlast);
}